// round 9
// baseline (speedup 1.0000x reference)
#include <cuda_runtime.h>

// gconv_19301583028599 — adaptive graph conv as fused flash-attention.
// f32x2 v3: 4 concurrent key-subtiles, transposed P (LDS.128), swizzled V/K,
// register prefetch of next K/V tile hidden under PV.
//
// y = softmax(relu(adj @ adj^T)) @ X      (X = x transposed to [N, B*INP])
// out[b,n,o] = x[b,n,:]·W0[n,:,o] + y[b,n,:]·W1[n,:,o] + bias[n,o]

#define NN   8192
#define BB   32
#define EMB  16
#define TQ   64
#define NH   4          // concurrent key-subtiles
#define KS   64         // keys per subtile
#define KITER (NH * KS) // 256 keys per iteration

#define PT_PITCH 72     // 288B: 16B-aligned rows -> LDS.128 P reads
#define PT_SUB   (KS * PT_PITCH)   // 4608

// smem layout (float offsets)
#define OFF_QTD  0                       // Qtd[d][dup 2r]  16 x 132
#define OFF_KT   2112                    // Kt[h][d][68]    4 x 16 x 68
#define OFF_VS   6464                    // Vs[h][k][64 sw] 4 x 64 x 64
#define OFF_PT   22848                   // Pt[h][k][row PT_PITCH] 4 x 64 x 72
#define OFF_LRED 41280                   // lred[h][64]
#define SMEM_FLOATS 41536                // 166,144 B
// overlays (after mainloop)
#define OFF_YS   OFF_PT                  // 64 x 68
#define OFF_ACC  (OFF_PT + 4352)        // 3 x 128 x 32
#define OFF_WPS  OFF_VS                  // 4096
#define OFF_BPS  (OFF_VS + 4096)        // 1024

typedef unsigned long long u64;

__device__ float g_Xt[NN * 64];   // Xt[m][2b+c] = x[b][m][c]

__global__ void transpose_x_kernel(const float* __restrict__ x) {
    int m = blockIdx.x * blockDim.x + threadIdx.x;
    if (m >= NN) return;
    float row[64];
#pragma unroll
    for (int b = 0; b < BB; b++) {
        float2 v = *(const float2*)(x + ((size_t)b * NN + m) * 2);
        row[2 * b] = v.x;  row[2 * b + 1] = v.y;
    }
    float4* dst = (float4*)(g_Xt + (size_t)m * 64);
#pragma unroll
    for (int q = 0; q < 16; q++) dst[q] = ((float4*)row)[q];
}

__device__ __forceinline__ u64 ffma2(u64 a, u64 b, u64 c) {
    u64 d;
    asm("fma.rn.f32x2 %0, %1, %2, %3;" : "=l"(d) : "l"(a), "l"(b), "l"(c));
    return d;
}
__device__ __forceinline__ u64 add2(u64 a, u64 b) {
    u64 d;
    asm("add.rn.f32x2 %0, %1, %2;" : "=l"(d) : "l"(a), "l"(b));
    return d;
}
__device__ __forceinline__ float2 unpk(u64 v) {
    float2 r;
    asm("mov.b64 {%0, %1}, %2;" : "=f"(r.x), "=f"(r.y) : "l"(v));
    return r;
}
__device__ __forceinline__ u64 pk2(float v) {   // (v, v)
    u64 d;
    asm("mov.b64 %0, {%1, %1};" : "=l"(d) : "f"(v));
    return d;
}

extern __shared__ float smf[];

__global__ __launch_bounds__(512, 1) void gconv_attn_kernel(
    const float* __restrict__ adj,
    const float* __restrict__ wp,
    const float* __restrict__ bp,
    float* __restrict__ out)
{
    float* Qtd  = smf + OFF_QTD;
    float* Kt   = smf + OFF_KT;
    float* Vs   = smf + OFF_VS;
    float* Pt   = smf + OFF_PT;
    float* lred = smf + OFF_LRED;

    const int tid  = threadIdx.x;
    const int half = tid >> 7;          // 0..3 key-subtile
    const int t7   = tid & 127;
    const int i4   = t7 >> 3;           // 0..15: rows 4*i4 .. 4*i4+3
    const int j8   = t7 & 7;            // 0..7 : cols/keys 8*j8 .. 8*j8+7
    const int n0   = blockIdx.x * TQ;

    // swizzled quad offsets for this thread's two 16B quads (quads 2j8, 2j8+1)
    const int qa = 2 * j8, qb = 2 * j8 + 1;
    const int offA = 4 * (qa ^ (qa >> 3));
    const int offB = 4 * (qb ^ (qb >> 3));

    // stage Qtd (duplicated): Qtd[d][2r,2r+1] = adj[n0+r][d]
#pragma unroll
    for (int t = 0; t < 2; t++) {
        int idx = tid + 512 * t;
        int r = idx >> 4, d = idx & 15;
        float v = adj[(n0 + r) * EMB + d];
        *(float2*)&Qtd[d * 132 + 2 * r] = make_float2(v, v);
    }

    const float* ktp  = Kt + half * 1088;
    const float* vsp  = Vs + half * 4096;
    float*       ptw  = Pt + half * PT_SUB;
    const float* ptr_ = ptw + 4 * i4;
    const float* qtp  = Qtd + 8 * i4;

    u64 a01[8], a23[8];
#pragma unroll
    for (int c = 0; c < 8; c++) { a01[c] = 0; a23[c] = 0; }
    float l0 = 0.f, l1 = 0.f, l2 = 0.f, l3 = 0.f;

    const int sd = tid & 15, skr = tid >> 4;   // K staging ids

    // prefetch tile 0 into registers
    float  kpf[8];
    float4 vpf[8];
#pragma unroll
    for (int m = 0; m < 8; m++)
        kpf[m] = adj[(skr + 32 * m) * EMB + sd];
#pragma unroll
    for (int t = 0; t < 8; t++) {
        int idx = tid + 512 * t;
        vpf[t] = *(const float4*)(g_Xt + (size_t)(idx >> 4) * 64 + 4 * (idx & 15));
    }

    for (int kt = 0; kt < NN; kt += KITER) {
        __syncthreads();   // prev PV done: Kt/Vs safe to overwrite
        // ---- stage K (transposed, quad-swizzled) + V from prefetch regs ----
#pragma unroll
        for (int m = 0; m < 8; m++) {
            int g = skr + 32 * m;                  // global key 0..255
            int h = g >> 6, k = g & 63;
            int q = k >> 2, p = k & 3;
            Kt[h * 1088 + sd * 68 + 4 * (q ^ (q >> 3)) + p] = kpf[m];
        }
#pragma unroll
        for (int t = 0; t < 8; t++) {
            int idx = tid + 512 * t;               // 0..4095
            int row = idx >> 4, q = idx & 15;
            *(float4*)&Vs[(row >> 6) * 4096 + (row & 63) * 64 + 4 * (q ^ (q >> 3))] = vpf[t];
        }
        __syncthreads();

        // ---- scores: s[r][kp] = pair of scores (row r) x (keys 8j8+2kp, +2kp+1) ----
        u64 s[16];
#pragma unroll
        for (int t = 0; t < 16; t++) s[t] = 0;
#pragma unroll
        for (int d = 0; d < EMB; d++) {
            const float* kd_ = ktp + d * 68;
            ulonglong2 kA = *(const ulonglong2*)(kd_ + offA);   // key-pairs (0,1),(2,3)
            ulonglong2 kB = *(const ulonglong2*)(kd_ + offB);   // key-pairs (4,5),(6,7)
            const float* qd_ = qtp + d * 132;
            ulonglong2 qA = *(const ulonglong2*)(qd_);          // dup(r0), dup(r1)
            ulonglong2 qB = *(const ulonglong2*)(qd_ + 4);      // dup(r2), dup(r3)
            s[0]  = ffma2(qA.x, kA.x, s[0]);  s[1]  = ffma2(qA.x, kA.y, s[1]);
            s[2]  = ffma2(qA.x, kB.x, s[2]);  s[3]  = ffma2(qA.x, kB.y, s[3]);
            s[4]  = ffma2(qA.y, kA.x, s[4]);  s[5]  = ffma2(qA.y, kA.y, s[5]);
            s[6]  = ffma2(qA.y, kB.x, s[6]);  s[7]  = ffma2(qA.y, kB.y, s[7]);
            s[8]  = ffma2(qB.x, kA.x, s[8]);  s[9]  = ffma2(qB.x, kA.y, s[9]);
            s[10] = ffma2(qB.x, kB.x, s[10]); s[11] = ffma2(qB.x, kB.y, s[11]);
            s[12] = ffma2(qB.y, kA.x, s[12]); s[13] = ffma2(qB.y, kA.y, s[13]);
            s[14] = ffma2(qB.y, kB.x, s[14]); s[15] = ffma2(qB.y, kB.y, s[15]);
        }
        // ---- p = exp(relu(s)) = max(exp(s), 1); partial row sums; P store ----
        float pr[4][8];
#pragma unroll
        for (int r = 0; r < 4; r++)
#pragma unroll
            for (int kp = 0; kp < 4; kp++) {
                float2 u = unpk(s[r * 4 + kp]);
                pr[r][2 * kp]     = fmaxf(__expf(u.x), 1.0f);
                pr[r][2 * kp + 1] = fmaxf(__expf(u.y), 1.0f);
            }
#pragma unroll
        for (int c = 0; c < 8; c++) {
            l0 += pr[0][c]; l1 += pr[1][c]; l2 += pr[2][c]; l3 += pr[3][c];
            *(float4*)(ptw + (8 * j8 + c) * PT_PITCH + 4 * i4) =
                make_float4(pr[0][c], pr[1][c], pr[2][c], pr[3][c]);
        }

        // ---- prefetch next tile (latency hidden under PV) ----
        {
            int ktn = kt + KITER; if (ktn >= NN) ktn = 0;
#pragma unroll
            for (int m = 0; m < 8; m++)
                kpf[m] = adj[(ktn + skr + 32 * m) * EMB + sd];
#pragma unroll
            for (int t = 0; t < 8; t++) {
                int idx = tid + 512 * t;
                vpf[t] = *(const float4*)(g_Xt + (size_t)(ktn + (idx >> 4)) * 64 + 4 * (idx & 15));
            }
        }
        __syncthreads();   // P ready

        // ---- PV: a[row-pair][col] += (p_r,p_r') * dup(v_col) ----
#pragma unroll 4
        for (int kk = 0; kk < KS; kk++) {
            ulonglong2 pp = *(const ulonglong2*)(ptr_ + kk * PT_PITCH);
            u64 p01 = pp.x, p23 = pp.y;
            const float* vk = vsp + kk * 64;
            ulonglong2 vA = *(const ulonglong2*)(vk + offA);   // cols 8j8..+3
            ulonglong2 vB = *(const ulonglong2*)(vk + offB);   // cols 8j8+4..+7
            float2 fa = unpk(vA.x), fb = unpk(vA.y), fc = unpk(vB.x), fd = unpk(vB.y);
            u64 d0 = pk2(fa.x), d1 = pk2(fa.y), d2 = pk2(fb.x), d3 = pk2(fb.y);
            u64 d4 = pk2(fc.x), d5 = pk2(fc.y), d6 = pk2(fd.x), d7 = pk2(fd.y);
            a01[0] = ffma2(p01, d0, a01[0]);  a23[0] = ffma2(p23, d0, a23[0]);
            a01[1] = ffma2(p01, d1, a01[1]);  a23[1] = ffma2(p23, d1, a23[1]);
            a01[2] = ffma2(p01, d2, a01[2]);  a23[2] = ffma2(p23, d2, a23[2]);
            a01[3] = ffma2(p01, d3, a01[3]);  a23[3] = ffma2(p23, d3, a23[3]);
            a01[4] = ffma2(p01, d4, a01[4]);  a23[4] = ffma2(p23, d4, a23[4]);
            a01[5] = ffma2(p01, d5, a01[5]);  a23[5] = ffma2(p23, d5, a23[5]);
            a01[6] = ffma2(p01, d6, a01[6]);  a23[6] = ffma2(p23, d6, a23[6]);
            a01[7] = ffma2(p01, d7, a01[7]);  a23[7] = ffma2(p23, d7, a23[7]);
        }
    }
    __syncthreads();   // S1: all PV (reads of Pt/Vs) done

    // row-sum reduce over j8 (lane bits 0..2), store per (half, row)
    l0 += __shfl_xor_sync(0xffffffffu, l0, 1);
    l0 += __shfl_xor_sync(0xffffffffu, l0, 2);
    l0 += __shfl_xor_sync(0xffffffffu, l0, 4);
    l1 += __shfl_xor_sync(0xffffffffu, l1, 1);
    l1 += __shfl_xor_sync(0xffffffffu, l1, 2);
    l1 += __shfl_xor_sync(0xffffffffu, l1, 4);
    l2 += __shfl_xor_sync(0xffffffffu, l2, 1);
    l2 += __shfl_xor_sync(0xffffffffu, l2, 2);
    l2 += __shfl_xor_sync(0xffffffffu, l2, 4);
    l3 += __shfl_xor_sync(0xffffffffu, l3, 1);
    l3 += __shfl_xor_sync(0xffffffffu, l3, 2);
    l3 += __shfl_xor_sync(0xffffffffu, l3, 4);
    if ((tid & 7) == 0)
        *(float4*)&lred[half * 64 + 4 * i4] = make_float4(l0, l1, l2, l3);

    // halves 1..3 stage their partial accumulators (Pt region overlay)
    if (half != 0) {
        float* st = smf + OFF_ACC + (size_t)((half - 1) * 128 + t7) * 32;
#pragma unroll
        for (int c = 0; c < 8; c++) {
            *(u64*)(st + 4 * c)      = a01[c];
            *(u64*)(st + 4 * c + 2)  = a23[c];
        }
    }
    // stage pools into Vs overlay
    float* wpsm = smf + OFF_WPS;
    float* bpsm = smf + OFF_BPS;
    ((float4*)wpsm)[tid]       = ((const float4*)wp)[tid];
    ((float4*)wpsm)[tid + 512] = ((const float4*)wp)[tid + 512];
    if (tid < 256) ((float4*)bpsm)[tid] = ((const float4*)bp)[tid];
    __syncthreads();   // S2

    float* Ysm = smf + OFF_YS;
    if (half == 0) {
        // merge 4 partials
#pragma unroll
        for (int h = 0; h < 3; h++) {
            const float* st = smf + OFF_ACC + (size_t)(h * 128 + t7) * 32;
#pragma unroll
            for (int c = 0; c < 8; c++) {
                a01[c] = add2(a01[c], *(const u64*)(st + 4 * c));
                a23[c] = add2(a23[c], *(const u64*)(st + 4 * c + 2));
            }
        }
        // denominators
        float4 La = *(const float4*)&lred[4 * i4];
        float4 Lb = *(const float4*)&lred[64 + 4 * i4];
        float4 Lc = *(const float4*)&lred[128 + 4 * i4];
        float4 Ld = *(const float4*)&lred[192 + 4 * i4];
        float inv0 = 1.f / (La.x + Lb.x + Lc.x + Ld.x);
        float inv1 = 1.f / (La.y + Lb.y + Lc.y + Ld.y);
        float inv2 = 1.f / (La.z + Lb.z + Lc.z + Ld.z);
        float inv3 = 1.f / (La.w + Lb.w + Lc.w + Ld.w);
        // normalize + write y tile (natural col order, pitch 68)
        float y0[8], y1[8], y2[8], y3[8];
#pragma unroll
        for (int c = 0; c < 8; c++) {
            float2 u = unpk(a01[c]); float2 w = unpk(a23[c]);
            y0[c] = u.x * inv0; y1[c] = u.y * inv1;
            y2[c] = w.x * inv2; y3[c] = w.y * inv3;
        }
        int rbase = 4 * i4;
        *(float4*)&Ysm[(rbase + 0) * 68 + 8 * j8]     = *(float4*)&y0[0];
        *(float4*)&Ysm[(rbase + 0) * 68 + 8 * j8 + 4] = *(float4*)&y0[4];
        *(float4*)&Ysm[(rbase + 1) * 68 + 8 * j8]     = *(float4*)&y1[0];
        *(float4*)&Ysm[(rbase + 1) * 68 + 8 * j8 + 4] = *(float4*)&y1[4];
        *(float4*)&Ysm[(rbase + 2) * 68 + 8 * j8]     = *(float4*)&y2[0];
        *(float4*)&Ysm[(rbase + 2) * 68 + 8 * j8 + 4] = *(float4*)&y2[4];
        *(float4*)&Ysm[(rbase + 3) * 68 + 8 * j8]     = *(float4*)&y3[0];
        *(float4*)&Ysm[(rbase + 3) * 68 + 8 * j8 + 4] = *(float4*)&y3[4];
    }
    __syncthreads();   // S3

    // ---- epilogue: out[b,n,o] = bias + x·W0 + y·W1 ----
    const int o  = tid & 63;
    const int ng = tid >> 6;   // 0..7, 8 rows each
#pragma unroll
    for (int q = 0; q < 8; q++) {
        int n = ng * 8 + q;
        float w00 = 0.f, w01 = 0.f, w10 = 0.f, w11 = 0.f, bbv = 0.f;
#pragma unroll
        for (int d = 0; d < EMB; d++) {
            float a = Qtd[d * 132 + 2 * n];
            const float* wrow = wpsm + d * 256 + o;   // (d*4 + 2k + i)*64 + o
            w00 += a * wrow[0];
            w01 += a * wrow[64];
            w10 += a * wrow[128];
            w11 += a * wrow[192];
            bbv += a * bpsm[d * 64 + o];
        }
        int gn = n0 + n;
        const float* xrow = g_Xt + (size_t)gn * 64;
        const float* yrow = Ysm + n * 68;
        float* orow = out + (size_t)gn * 64 + o;
#pragma unroll 4
        for (int b = 0; b < BB; b++) {
            float2 xv = *(const float2*)(xrow + 2 * b);
            float2 yv = *(const float2*)(yrow + 2 * b);
            orow[(size_t)b * (NN * 64)] = bbv + xv.x * w00 + xv.y * w01 + yv.x * w10 + yv.y * w11;
        }
    }
}

extern "C" void kernel_launch(void* const* d_in, const int* in_sizes, int n_in,
                              void* d_out, int out_size) {
    const float* x   = (const float*)d_in[0];   // [32, 8192, 2]
    const float* adj = (const float*)d_in[1];   // [8192, 16]
    const float* wp  = (const float*)d_in[2];   // [16, 2, 2, 64]
    const float* bp  = (const float*)d_in[3];   // [16, 64]
    float* out = (float*)d_out;                 // [32, 8192, 64]

    cudaFuncSetAttribute(gconv_attn_kernel,
                         cudaFuncAttributeMaxDynamicSharedMemorySize,
                         SMEM_FLOATS * (int)sizeof(float));
    transpose_x_kernel<<<NN / 256, 256>>>(x);
    gconv_attn_kernel<<<NN / TQ, 512, SMEM_FLOATS * sizeof(float)>>>(adj, wp, bp, out);
}

// round 14
// speedup vs baseline: 1.2128x; 1.2128x over previous
#include <cuda_runtime.h>

// gconv_19301583028599 — adaptive graph conv as fused flash-attention.
// f32x2 v4b: crossbar-minimized; fixes v4's lred/wpsm smem overlay collision.
// 8x8 PV thread tiles (8 key-groups, deferred merge), Q natural + on-the-fly
// dup, P key-transposed with LDS.128 path.
//
// y = softmax(relu(adj @ adj^T)) @ X      (X = x transposed to [N, B*INP])
// out[b,n,o] = x[b,n,:]·W0[n,:,o] + y[b,n,:]·W1[n,:,o] + bias[n,o]

#define NN   8192
#define BB   32
#define EMB  16
#define TQ   64
#define KS   64         // keys per subtile
#define KITER 256       // keys per iteration (4 subtiles)

#define QT_P 68
#define KT_P 68
#define PT_P 72
#define PT_SUB (KS * PT_P)   // 4608

// smem layout (float offsets)
#define OFF_QT   0               // Qt[d][r]            16 x 68   = 1088
#define OFF_KT   1088            // Kt[h][d][64 sw]     4 x 16 x 68 = 4352
#define OFF_VS   5440            // Vs[h][k][64 sw]     4 x 64 x 64 = 16384
#define OFF_PT   21824           // Pt[h][rho][row 72]  4 x 64 x 72 = 18432 (ends 40256)
// overlays (after mainloop)
#define OFF_ACC2 1088            // 512 threads x 64 floats = 32768 (ends 33856)
#define OFF_YS   33856           // 64 x 68 = 4352 (ends 38208)
#define OFF_WPS  38208           // 4096 (ends 42304)
#define OFF_BPS  42304           // 1024 (ends 43328)
#define OFF_LRED 43328           // lred[half][64] = 256 — OUTSIDE all overlays
#define SMEM_FLOATS 43584        // 174,336 B

typedef unsigned long long u64;

__device__ float g_Xt[NN * 64];   // Xt[m][2b+c] = x[b][m][c]

__global__ void transpose_x_kernel(const float* __restrict__ x) {
    int m = blockIdx.x * blockDim.x + threadIdx.x;
    if (m >= NN) return;
    float row[64];
#pragma unroll
    for (int b = 0; b < BB; b++) {
        float2 v = *(const float2*)(x + ((size_t)b * NN + m) * 2);
        row[2 * b] = v.x;  row[2 * b + 1] = v.y;
    }
    float4* dst = (float4*)(g_Xt + (size_t)m * 64);
#pragma unroll
    for (int q = 0; q < 16; q++) dst[q] = ((float4*)row)[q];
}

__device__ __forceinline__ u64 ffma2(u64 a, u64 b, u64 c) {
    u64 d;
    asm("fma.rn.f32x2 %0, %1, %2, %3;" : "=l"(d) : "l"(a), "l"(b), "l"(c));
    return d;
}
__device__ __forceinline__ u64 add2(u64 a, u64 b) {
    u64 d;
    asm("add.rn.f32x2 %0, %1, %2;" : "=l"(d) : "l"(a), "l"(b));
    return d;
}
__device__ __forceinline__ float2 unpk(u64 v) {
    float2 r;
    asm("mov.b64 {%0, %1}, %2;" : "=f"(r.x), "=f"(r.y) : "l"(v));
    return r;
}
__device__ __forceinline__ u64 pk2(float v) {   // (v, v)
    u64 d;
    asm("mov.b64 %0, {%1, %1};" : "=l"(d) : "f"(v));
    return d;
}

extern __shared__ float smf[];

__global__ __launch_bounds__(512, 1) void gconv_attn_kernel(
    const float* __restrict__ adj,
    const float* __restrict__ wp,
    const float* __restrict__ bp,
    float* __restrict__ out)
{
    float* Qt   = smf + OFF_QT;
    float* Kt   = smf + OFF_KT;
    float* Vs   = smf + OFF_VS;
    float* Pt   = smf + OFF_PT;
    float* lred = smf + OFF_LRED;

    const int tid  = threadIdx.x;
    // scores mapping
    const int half = tid >> 7;          // 0..3 key-subtile
    const int t7   = tid & 127;
    const int i4   = t7 >> 3;           // 0..15: rows 4*i4..+3
    const int j8   = t7 & 7;            // 0..7 : keys 8*j8..+7 (within subtile)
    // PV mapping
    const int h2   = tid >> 6;          // 0..7 key-group
    const int hh   = h2 >> 1;           // subtile
    const int tb   = (h2 & 1) * 4;      // key t-base
    const int i8   = (tid >> 3) & 7;    // rows 8*i8..+7
    // j8 (tid&7) doubles as PV col-group
    const int n0   = blockIdx.x * TQ;

    // swizzled quad offsets (quads 2j8, 2j8+1)
    const int qa = 2 * j8, qb = 2 * j8 + 1;
    const int offA = 4 * (qa ^ (qa >> 3));
    const int offB = 4 * (qb ^ (qb >> 3));

    // stage Qt (natural): Qt[d][r] = adj[n0+r][d]
#pragma unroll
    for (int t = 0; t < 2; t++) {
        int idx = tid + 512 * t;
        int r = idx >> 4, d = idx & 15;
        Qt[d * QT_P + r] = adj[(n0 + r) * EMB + d];
    }

    const float* ktp   = Kt + half * (EMB * KT_P);
    float*       ptw   = Pt + half * PT_SUB + j8 * PT_P + 4 * i4;   // + 8c*PT_P per c
    const float* qtp   = Qt + 4 * i4;
    const float* pbase = Pt + hh * PT_SUB + 8 * i8;
    const float* vbase = Vs + hh * 4096;

    u64 acc[4][8];
#pragma unroll
    for (int rp = 0; rp < 4; rp++)
#pragma unroll
        for (int c = 0; c < 8; c++) acc[rp][c] = 0;
    float l0 = 0.f, l1 = 0.f, l2 = 0.f, l3 = 0.f;

    const int sd = tid & 15, skr = tid >> 4;   // K staging ids

    for (int kt = 0; kt < NN; kt += KITER) {
        __syncthreads();   // prev PV done: Kt/Vs safe to overwrite
        // ---- stage K (transposed, quad-swizzled): Kt[h][d][k] ----
#pragma unroll
        for (int m = 0; m < 8; m++) {
            int g = skr + 32 * m;                  // global key 0..255
            float v = adj[(kt + g) * EMB + sd];
            int h = g >> 6, k = g & 63;
            int q = k >> 2, p = k & 3;
            Kt[h * (EMB * KT_P) + sd * KT_P + 4 * (q ^ (q >> 3)) + p] = v;
        }
        // ---- stage V (quad-swizzled rows) ----
#pragma unroll
        for (int t = 0; t < 8; t++) {
            int idx = tid + 512 * t;               // 0..4095
            int row = idx >> 4, q = idx & 15;
            float4 v = *(const float4*)(g_Xt + (size_t)(kt + row) * 64 + 4 * q);
            *(float4*)&Vs[(row >> 6) * 4096 + (row & 63) * 64 + 4 * (q ^ (q >> 3))] = v;
        }
        __syncthreads();

        // ---- scores: Q natural pairs + dup-on-the-fly; key-pairs from Kt ----
        u64 s[16];
#pragma unroll
        for (int t = 0; t < 16; t++) s[t] = 0;
#pragma unroll
        for (int d = 0; d < EMB; d++) {
            float4 qv = *(const float4*)(qtp + d * QT_P);      // rows 4i4..+3
            u64 q0 = pk2(qv.x), q1 = pk2(qv.y), q2 = pk2(qv.z), q3 = pk2(qv.w);
            const float* kd_ = ktp + d * KT_P;
            ulonglong2 kA = *(const ulonglong2*)(kd_ + offA);  // key pairs (0,1),(2,3)
            ulonglong2 kB = *(const ulonglong2*)(kd_ + offB);  // key pairs (4,5),(6,7)
            s[0]  = ffma2(q0, kA.x, s[0]);  s[1]  = ffma2(q0, kA.y, s[1]);
            s[2]  = ffma2(q0, kB.x, s[2]);  s[3]  = ffma2(q0, kB.y, s[3]);
            s[4]  = ffma2(q1, kA.x, s[4]);  s[5]  = ffma2(q1, kA.y, s[5]);
            s[6]  = ffma2(q1, kB.x, s[6]);  s[7]  = ffma2(q1, kB.y, s[7]);
            s[8]  = ffma2(q2, kA.x, s[8]);  s[9]  = ffma2(q2, kA.y, s[9]);
            s[10] = ffma2(q2, kB.x, s[10]); s[11] = ffma2(q2, kB.y, s[11]);
            s[12] = ffma2(q3, kA.x, s[12]); s[13] = ffma2(q3, kA.y, s[13]);
            s[14] = ffma2(q3, kB.x, s[14]); s[15] = ffma2(q3, kB.y, s[15]);
        }
        // ---- p = exp(relu(s)) = max(exp(s), 1); row sums; P store ----
        float pr[4][8];
#pragma unroll
        for (int r = 0; r < 4; r++)
#pragma unroll
            for (int kp = 0; kp < 4; kp++) {
                float2 u = unpk(s[r * 4 + kp]);
                pr[r][2 * kp]     = fmaxf(__expf(u.x), 1.0f);
                pr[r][2 * kp + 1] = fmaxf(__expf(u.y), 1.0f);
            }
#pragma unroll
        for (int c = 0; c < 8; c++) {
            l0 += pr[0][c]; l1 += pr[1][c]; l2 += pr[2][c]; l3 += pr[3][c];
            // key k = 8*j8 + c  ->  row rho = 8*c + j8
            *(float4*)(ptw + 8 * c * PT_P) =
                make_float4(pr[0][c], pr[1][c], pr[2][c], pr[3][c]);
        }
        __syncthreads();   // P ready

        // ---- PV (8x8 tile, 32 keys): rho = 8m + t, key k = 8t + m ----
#pragma unroll 8
        for (int kk = 0; kk < 32; kk++) {
            int t = tb + (kk & 3), m = kk >> 2;
            const float* pk_ = pbase + (8 * m + t) * PT_P;
            ulonglong2 pp0 = *(const ulonglong2*)pk_;          // row pairs (0,1),(2,3)
            ulonglong2 pp1 = *(const ulonglong2*)(pk_ + 4);    // row pairs (4,5),(6,7)
            const float* vk = vbase + (8 * t + m) * 64;
            ulonglong2 vA = *(const ulonglong2*)(vk + offA);   // cols 8j8..+3
            ulonglong2 vB = *(const ulonglong2*)(vk + offB);   // cols 8j8+4..+7
            float2 fa = unpk(vA.x), fb = unpk(vA.y), fc = unpk(vB.x), fd = unpk(vB.y);
            u64 d0 = pk2(fa.x), d1 = pk2(fa.y), d2 = pk2(fb.x), d3 = pk2(fb.y);
            u64 d4 = pk2(fc.x), d5 = pk2(fc.y), d6 = pk2(fd.x), d7 = pk2(fd.y);
            u64 p0 = pp0.x, p1 = pp0.y, p2 = pp1.x, p3 = pp1.y;
            acc[0][0] = ffma2(p0, d0, acc[0][0]); acc[0][1] = ffma2(p0, d1, acc[0][1]);
            acc[0][2] = ffma2(p0, d2, acc[0][2]); acc[0][3] = ffma2(p0, d3, acc[0][3]);
            acc[0][4] = ffma2(p0, d4, acc[0][4]); acc[0][5] = ffma2(p0, d5, acc[0][5]);
            acc[0][6] = ffma2(p0, d6, acc[0][6]); acc[0][7] = ffma2(p0, d7, acc[0][7]);
            acc[1][0] = ffma2(p1, d0, acc[1][0]); acc[1][1] = ffma2(p1, d1, acc[1][1]);
            acc[1][2] = ffma2(p1, d2, acc[1][2]); acc[1][3] = ffma2(p1, d3, acc[1][3]);
            acc[1][4] = ffma2(p1, d4, acc[1][4]); acc[1][5] = ffma2(p1, d5, acc[1][5]);
            acc[1][6] = ffma2(p1, d6, acc[1][6]); acc[1][7] = ffma2(p1, d7, acc[1][7]);
            acc[2][0] = ffma2(p2, d0, acc[2][0]); acc[2][1] = ffma2(p2, d1, acc[2][1]);
            acc[2][2] = ffma2(p2, d2, acc[2][2]); acc[2][3] = ffma2(p2, d3, acc[2][3]);
            acc[2][4] = ffma2(p2, d4, acc[2][4]); acc[2][5] = ffma2(p2, d5, acc[2][5]);
            acc[2][6] = ffma2(p2, d6, acc[2][6]); acc[2][7] = ffma2(p2, d7, acc[2][7]);
            acc[3][0] = ffma2(p3, d0, acc[3][0]); acc[3][1] = ffma2(p3, d1, acc[3][1]);
            acc[3][2] = ffma2(p3, d2, acc[3][2]); acc[3][3] = ffma2(p3, d3, acc[3][3]);
            acc[3][4] = ffma2(p3, d4, acc[3][4]); acc[3][5] = ffma2(p3, d5, acc[3][5]);
            acc[3][6] = ffma2(p3, d6, acc[3][6]); acc[3][7] = ffma2(p3, d7, acc[3][7]);
        }
    }
    __syncthreads();   // S1: all PV reads done

    // ---- row-sum reduce over j8 (lane bits 0..2) ----
    l0 += __shfl_xor_sync(0xffffffffu, l0, 1);
    l0 += __shfl_xor_sync(0xffffffffu, l0, 2);
    l0 += __shfl_xor_sync(0xffffffffu, l0, 4);
    l1 += __shfl_xor_sync(0xffffffffu, l1, 1);
    l1 += __shfl_xor_sync(0xffffffffu, l1, 2);
    l1 += __shfl_xor_sync(0xffffffffu, l1, 4);
    l2 += __shfl_xor_sync(0xffffffffu, l2, 1);
    l2 += __shfl_xor_sync(0xffffffffu, l2, 2);
    l2 += __shfl_xor_sync(0xffffffffu, l2, 4);
    l3 += __shfl_xor_sync(0xffffffffu, l3, 1);
    l3 += __shfl_xor_sync(0xffffffffu, l3, 2);
    l3 += __shfl_xor_sync(0xffffffffu, l3, 4);
    if ((tid & 7) == 0)
        *(float4*)&lred[half * 64 + 4 * i4] = make_float4(l0, l1, l2, l3);

    // ---- stage all partial accumulators (overlay over Kt/Vs/Pt-front) ----
    {
        float* st = smf + OFF_ACC2 + (size_t)tid * 64;   // [rp][c] at rp*16 + 2c
#pragma unroll
        for (int rp = 0; rp < 4; rp++)
#pragma unroll
            for (int c = 0; c < 8; c += 2) {
                *(u64*)(st + rp * 16 + 2 * c)     = acc[rp][c];
                *(u64*)(st + rp * 16 + 2 * c + 2) = acc[rp][c + 1];
            }
    }
    // stage pools
    float* wpsm = smf + OFF_WPS;
    float* bpsm = smf + OFF_BPS;
    ((float4*)wpsm)[tid]       = ((const float4*)wp)[tid];
    ((float4*)wpsm)[tid + 512] = ((const float4*)wp)[tid + 512];
    if (tid < 256) ((float4*)bpsm)[tid] = ((const float4*)bp)[tid];
    __syncthreads();   // S2

    // ---- merge 8 partials, normalize, write Ysm ----
    float* Ysm = smf + OFF_YS;
    {
        const int u0 = 4 * tid;              // u64 ids u0..u0+3 (2048 total)
        const int RP = u0 >> 6;              // row-pair 0..31
        const int c0 = u0 & 63;
        const int r0 = 2 * RP;
        float La = lred[r0]     + lred[64 + r0]     + lred[128 + r0]     + lred[192 + r0];
        float Lb = lred[r0 + 1] + lred[64 + r0 + 1] + lred[128 + r0 + 1] + lred[192 + r0 + 1];
        float inv0 = 1.f / La, inv1 = 1.f / Lb;
        const int i8m = RP >> 2, rpm = RP & 3;
#pragma unroll
        for (int m4 = 0; m4 < 4; m4++) {
            int c = c0 + m4;
            int j8m = c >> 3, cm = c & 7;
            const float* base = smf + OFF_ACC2 +
                (size_t)((i8m * 8 + j8m) * 64 + rpm * 16 + 2 * cm);
            u64 sum = *(const u64*)base;
#pragma unroll
            for (int h = 1; h < 8; h++)
                sum = add2(sum, *(const u64*)(base + (size_t)h * 4096));
            float2 yv = unpk(sum);
            Ysm[r0 * 68 + c]       = yv.x * inv0;
            Ysm[(r0 + 1) * 68 + c] = yv.y * inv1;
        }
    }
    __syncthreads();   // S3

    // ---- epilogue: out[b,n,o] = bias + x·W0 + y·W1 ----
    const int o  = tid & 63;
    const int ng = tid >> 6;   // 0..7, 8 rows each
#pragma unroll
    for (int q = 0; q < 8; q++) {
        int n = ng * 8 + q;
        float w00 = 0.f, w01 = 0.f, w10 = 0.f, w11 = 0.f, bbv = 0.f;
#pragma unroll
        for (int d = 0; d < EMB; d++) {
            float a = Qt[d * QT_P + n];
            const float* wrow = wpsm + d * 256 + o;   // (d*4 + 2k + i)*64 + o
            w00 += a * wrow[0];
            w01 += a * wrow[64];
            w10 += a * wrow[128];
            w11 += a * wrow[192];
            bbv += a * bpsm[d * 64 + o];
        }
        int gn = n0 + n;
        const float* xrow = g_Xt + (size_t)gn * 64;
        const float* yrow = Ysm + n * 68;
        float* orow = out + (size_t)gn * 64 + o;
#pragma unroll 4
        for (int b = 0; b < BB; b++) {
            float2 xv = *(const float2*)(xrow + 2 * b);
            float2 yv = *(const float2*)(yrow + 2 * b);
            orow[(size_t)b * (NN * 64)] = bbv + xv.x * w00 + xv.y * w01 + yv.x * w10 + yv.y * w11;
        }
    }
}

extern "C" void kernel_launch(void* const* d_in, const int* in_sizes, int n_in,
                              void* d_out, int out_size) {
    const float* x   = (const float*)d_in[0];   // [32, 8192, 2]
    const float* adj = (const float*)d_in[1];   // [8192, 16]
    const float* wp  = (const float*)d_in[2];   // [16, 2, 2, 64]
    const float* bp  = (const float*)d_in[3];   // [16, 64]
    float* out = (float*)d_out;                 // [32, 8192, 64]

    cudaFuncSetAttribute(gconv_attn_kernel,
                         cudaFuncAttributeMaxDynamicSharedMemorySize,
                         SMEM_FLOATS * (int)sizeof(float));
    transpose_x_kernel<<<NN / 256, 256>>>(x);
    gconv_attn_kernel<<<NN / TQ, 512, SMEM_FLOATS * sizeof(float)>>>(adj, wp, bp, out);
}